// round 5
// baseline (speedup 1.0000x reference)
#include <cuda_runtime.h>
#include <cstdint>

// Problem constants
#define B_  512
#define T_  512
#define NQ_ 1000
#define K_  5
#define M_  50
#define DK_ 64
#define DV_ 256
#define DF_ 50
#define BT_ (B_*T_)   // 262144

// ---------------- scratch (device globals; no allocation allowed) ----------------
__device__ __align__(16) float g_Tw   [(NQ_+1)*M_];      // softmaxed attention per q
__device__ __align__(16) float g_Tsq  [(NQ_+1)*DF_];     // qe @ summary_W[256:]
__device__ __align__(16) float g_Tbeta[(NQ_+1)*4];       // qe @ thresh_W + b
__device__ __align__(16) float g_Tdisc[(NQ_+1)];         // qe @ disc_W[50:] + b
__device__ __align__(16) float g_Tcorn[(NQ_+1)*4];       // qe @ corn_W[50:] + b
__device__ __align__(16) float g_E1[NQ_*DV_], g_E2[NQ_*DV_];
__device__ __align__(16) float g_A1[NQ_*DV_], g_A2[NQ_*DV_];
__device__ __align__(16) float g_be[DV_], g_ba[DV_];
__device__ __align__(16) float g_Te[(NQ_+1)*K_*DV_];     // sigmoid(erase pre) per (q,r)
__device__ __align__(16) float g_Ta[(NQ_+1)*K_*DV_];     // tanh(add pre)  per (q,r)
__device__ __align__(16) float g_reads[BT_*DV_];         // 268 MB

__device__ __forceinline__ float sigmoidf_(float x) { return 1.f/(1.f+expf(-x)); }

// ---- packed f32x2 helpers (FFMA2 path — only reachable via PTX) ----
typedef unsigned long long ull;
__device__ __forceinline__ ull fma2(ull a, ull b, ull c) {
    ull d; asm("fma.rn.f32x2 %0, %1, %2, %3;" : "=l"(d) : "l"(a), "l"(b), "l"(c));
    return d;
}
__device__ __forceinline__ ull add2(ull a, ull b) {
    ull d; asm("add.rn.f32x2 %0, %1, %2;" : "=l"(d) : "l"(a), "l"(b));
    return d;
}
__device__ __forceinline__ ull pack2(float lo, float hi) {
    ull d; asm("mov.b64 %0, {%1, %2};" : "=l"(d) : "f"(lo), "f"(hi));
    return d;
}
__device__ __forceinline__ void unpack2(ull v, float& lo, float& hi) {
    asm("mov.b64 {%0, %1}, %2;" : "=f"(lo), "=f"(hi) : "l"(v));
}

// ---------------- P2': value_W @ {erase_W, add_W}, plus bias block ----------------
__global__ void p2_etables(const float* __restrict__ vW,
                           const float* __restrict__ We, const float* __restrict__ Wa,
                           const float* __restrict__ vb, const float* __restrict__ eb,
                           const float* __restrict__ ab) {
    __shared__ float vr1[8][DV_];
    __shared__ float vr2[8][DV_];
    int tid = threadIdx.x;
    if (blockIdx.x == 125) {            // bias path
        __shared__ float svb[DV_];
        svb[tid] = vb[tid];
        __syncthreads();
        float e = eb[tid], a = ab[tid];
        for (int k = 0; k < DV_; k++) {
            float x = svb[k];
            e = fmaf(x, We[k*DV_+tid], e);
            a = fmaf(x, Wa[k*DV_+tid], a);
        }
        g_be[tid] = e; g_ba[tid] = a;
        return;
    }
    int i0 = blockIdx.x * 8;
    #pragma unroll
    for (int i = 0; i < 8; i++) {
        vr1[i][tid] = vW[(i0+i)*DV_ + tid];
        vr2[i][tid] = vW[(NQ_ + i0+i)*DV_ + tid];
    }
    __syncthreads();
    float e1[8] = {0}, e2[8] = {0}, a1[8] = {0}, a2[8] = {0};
    int v = tid;
    for (int k = 0; k < DV_; k++) {
        float we = We[k*DV_ + v];
        float wa = Wa[k*DV_ + v];
        #pragma unroll
        for (int i = 0; i < 8; i++) {
            float x1 = vr1[i][k], x2 = vr2[i][k];
            e1[i] = fmaf(x1, we, e1[i]); e2[i] = fmaf(x2, we, e2[i]);
            a1[i] = fmaf(x1, wa, a1[i]); a2[i] = fmaf(x2, wa, a2[i]);
        }
    }
    #pragma unroll
    for (int i = 0; i < 8; i++) {
        g_E1[(i0+i)*DV_ + v] = e1[i]; g_E2[(i0+i)*DV_ + v] = e2[i];
        g_A1[(i0+i)*DV_ + v] = a1[i]; g_A2[(i0+i)*DV_ + v] = a2[i];
    }
}

// ---------------- P1: per-question tables ----------------
__global__ void p1_qtables(const float* __restrict__ qW, const float* __restrict__ Mk,
                           const float* __restrict__ sW,
                           const float* __restrict__ tW, const float* __restrict__ tb,
                           const float* __restrict__ dW, const float* __restrict__ db,
                           const float* __restrict__ cW, const float* __restrict__ cb) {
    __shared__ float qe[DK_];
    __shared__ float wl[M_];
    __shared__ float red[2];
    int q = blockIdx.x, tid = threadIdx.x;
    if (tid < DK_) qe[tid] = qW[q*DK_ + tid];
    __syncthreads();
    if (tid < 50) {
        float acc = 0.f;
        const float* mk = Mk + tid*DK_;
        #pragma unroll 16
        for (int k = 0; k < DK_; k++) acc = fmaf(qe[k], mk[k], acc);
        wl[tid] = acc;
    } else if (tid < 100) {
        int j = tid - 50; float acc = 0.f;
        for (int k = 0; k < DK_; k++) acc = fmaf(qe[k], sW[(DV_+k)*DF_ + j], acc);
        g_Tsq[q*DF_ + j] = acc;
    } else if (tid < 104) {
        int c = tid - 100; float acc = tb[c];
        for (int k = 0; k < DK_; k++) acc = fmaf(qe[k], tW[k*4 + c], acc);
        g_Tbeta[q*4 + c] = acc;
    } else if (tid == 104) {
        float acc = db[0];
        for (int k = 0; k < DK_; k++) acc = fmaf(qe[k], dW[50 + k], acc);
        g_Tdisc[q] = acc;
    } else if (tid < 109) {
        int c = tid - 105; float acc = cb[c];
        for (int k = 0; k < DK_; k++) acc = fmaf(qe[k], cW[(50+k)*4 + c], acc);
        g_Tcorn[q*4 + c] = acc;
    }
    __syncthreads();
    if (tid == 0) {
        float mx = wl[0];
        for (int m = 1; m < M_; m++) mx = fmaxf(mx, wl[m]);
        red[0] = mx;
    }
    __syncthreads();
    if (tid < M_) wl[tid] = expf(wl[tid] - red[0]);
    __syncthreads();
    if (tid == 0) {
        float s = 0.f;
        for (int m = 0; m < M_; m++) s += wl[m];
        red[1] = 1.f / s;
    }
    __syncthreads();
    if (tid < M_) g_Tw[q*M_ + tid] = wl[tid] * red[1];
}

// ---------------- P3: activation tables per (q,r) ----------------
__global__ void p3_acts() {
    int q = blockIdx.x / K_, r = blockIdx.x % K_;
    int v = threadIdx.x;
    float rs = (float)r * 0.25f;
    float pe = 0.f, pa = 0.f;
    if (q > 0) {
        int idx = q - 1;
        pe = fmaf(rs, g_E2[idx*DV_ + v], g_E1[idx*DV_ + v]);
        pa = fmaf(rs, g_A2[idx*DV_ + v], g_A1[idx*DV_ + v]);
    }
    pe += g_be[v]; pa += g_ba[v];
    int base = (q*K_ + r)*DV_ + v;
    g_Te[base] = sigmoidf_(pe);
    g_Ta[base] = tanhf(pa);
}

// ---------------- Scan v4: pack over m (no shfl), 128 thr, grid (2, 512) ----------
// Thread owns a SINGLE v column; Mv2[j] packs {Mv[2j][v], Mv[2j+1][v]}.
// w pairs {w_2j, w_2j+1} are contiguous floats in smem -> broadcast ulonglong2 LDS.
// Update: t1 = fma2(Mv, {-e,-e}, {a,a}); Mv = fma2({w,w'}, t1, Mv);
// read: acc += {w,w'} * Mv_old; final read = lo(acc)+hi(acc).
__global__ __launch_bounds__(128, 5) void scan_kernel(const int* __restrict__ qd,
                                                      const int* __restrict__ rd,
                                                      const float* __restrict__ Mv0) {
    __shared__ __align__(16) float w_s[2][56];   // 50 used, double-buffered
    int b   = blockIdx.y;
    int vb  = blockIdx.x;
    int tid = threadIdx.x;
    int v   = vb*128 + tid;
    ull Mv2[25];
    #pragma unroll
    for (int j = 0; j < 25; j++)
        Mv2[j] = pack2(Mv0[(2*j)*DV_ + v], Mv0[(2*j+1)*DV_ + v]);
    const int bT = b * T_;
    float* rout = g_reads + (size_t)bT * DV_ + v;

    int q0 = __ldg(qd + bT), r0 = __ldg(rd + bT);
    if (tid < 50) w_s[0][tid] = g_Tw[q0*M_ + tid];
    float ecur = g_Te[(q0*K_ + r0)*DV_ + v];
    float acur = g_Ta[(q0*K_ + r0)*DV_ + v];

    for (int t = 0; t < T_; t++) {
        __syncthreads();   // w_s[t&1] ready; prior readers of w_s[(t+1)&1] done
        if (t + 1 < T_) {
            int qn = __ldg(qd + bT + t + 1);
            int rn = __ldg(rd + bT + t + 1);
            if (tid < 50) w_s[(t + 1) & 1][tid] = g_Tw[qn*M_ + tid];
            ull ne2 = pack2(-ecur, -ecur);
            ull a2  = pack2(acur,  acur);
            // prefetch e/a for t+1
            int basen = (qn*K_ + rn)*DV_ + v;
            ecur = g_Te[basen];
            acur = g_Ta[basen];
            ull acc0 = 0ull, acc1 = 0ull;
            const float* wb = w_s[t & 1];
            #pragma unroll
            for (int j = 0; j < 12; j++) {
                ulonglong2 wv = *(const ulonglong2*)&wb[4*j];  // {w4j,w4j+1},{w4j+2,w4j+3}
                {
                    ull old = Mv2[2*j];
                    acc0 = fma2(wv.x, old, acc0);
                    ull t1 = fma2(old, ne2, a2);
                    Mv2[2*j] = fma2(wv.x, t1, old);
                }
                {
                    ull old = Mv2[2*j+1];
                    acc1 = fma2(wv.y, old, acc1);
                    ull t1 = fma2(old, ne2, a2);
                    Mv2[2*j+1] = fma2(wv.y, t1, old);
                }
            }
            {   // m = 48,49
                ull wlast = *(const ull*)&wb[48];
                ull old = Mv2[24];
                acc0 = fma2(wlast, old, acc0);
                ull t1 = fma2(old, ne2, a2);
                Mv2[24] = fma2(wlast, t1, old);
            }
            float lo, hi;
            unpack2(add2(acc0, acc1), lo, hi);
            rout[(size_t)t * DV_] = lo + hi;
        } else {
            // last step: no prefetch
            ull ne2 = pack2(-ecur, -ecur);
            ull a2  = pack2(acur,  acur);
            ull acc0 = 0ull, acc1 = 0ull;
            const float* wb = w_s[t & 1];
            #pragma unroll
            for (int j = 0; j < 12; j++) {
                ulonglong2 wv = *(const ulonglong2*)&wb[4*j];
                {
                    ull old = Mv2[2*j];
                    acc0 = fma2(wv.x, old, acc0);
                    ull t1 = fma2(old, ne2, a2);
                    Mv2[2*j] = fma2(wv.x, t1, old);
                }
                {
                    ull old = Mv2[2*j+1];
                    acc1 = fma2(wv.y, old, acc1);
                    ull t1 = fma2(old, ne2, a2);
                    Mv2[2*j+1] = fma2(wv.y, t1, old);
                }
            }
            {
                ull wlast = *(const ull*)&wb[48];
                ull old = Mv2[24];
                acc0 = fma2(wlast, old, acc0);
                ull t1 = fma2(old, ne2, a2);
                Mv2[24] = fma2(wlast, t1, old);
            }
            float lo, hi;
            unpack2(add2(acc0, acc1), lo, hi);
            rout[(size_t)t * DV_] = lo + hi;
        }
    }
}

// ---------------- Summary GEMM (row-pair packed f32x2) + fused heads ----------------
// Block: 64 rows x 64 cols (50 valid), 256 threads, GBK=16.  (verified in R2)
__global__ __launch_bounds__(256) void summary_heads(const float* __restrict__ sW,
                                                     const float* __restrict__ sb,
                                                     const int* __restrict__ qd,
                                                     const float* __restrict__ abW,
                                                     const float* __restrict__ abB,
                                                     const float* __restrict__ dW,
                                                     const float* __restrict__ cW,
                                                     float* __restrict__ out) {
    __shared__ __align__(16) float As[16][64];      // [k][row]
    __shared__ __align__(16) float Bs2[16][128];    // [k][col-pairs duplicated]
    __shared__ __align__(16) float sSum[64][53];    // stride 53 (odd) -> conflict-free
    __shared__ float sAb[DF_], sDw[DF_], sCw[DF_*4];
    int tid  = threadIdx.x;
    int row0 = blockIdx.x * 64;
    int tx = tid & 15, ty = tid >> 4;
    int arow = tid >> 2, ak4 = (tid & 3) * 4;   // A fill
    int bk = tid >> 4, bj4 = (tid & 15) * 4;    // B fill

    if (tid < DF_)  { sAb[tid] = abW[tid]; sDw[tid] = dW[tid]; }
    if (tid < DF_*4) sCw[tid] = cW[tid];

    ull acc[2][4];
    #pragma unroll
    for (int p = 0; p < 2; p++)
        #pragma unroll
        for (int c = 0; c < 4; c++) acc[p][c] = 0ull;

    for (int k0 = 0; k0 < DV_; k0 += 16) {
        float4 av = *(const float4*)(g_reads + (size_t)(row0 + arow)*DV_ + k0 + ak4);
        As[ak4+0][arow] = av.x; As[ak4+1][arow] = av.y;
        As[ak4+2][arow] = av.z; As[ak4+3][arow] = av.w;
        float b0 = (bj4+0 < DF_) ? sW[(k0+bk)*DF_ + bj4+0] : 0.f;
        float b1 = (bj4+1 < DF_) ? sW[(k0+bk)*DF_ + bj4+1] : 0.f;
        float b2 = (bj4+2 < DF_) ? sW[(k0+bk)*DF_ + bj4+2] : 0.f;
        float b3 = (bj4+3 < DF_) ? sW[(k0+bk)*DF_ + bj4+3] : 0.f;
        *(float4*)&Bs2[bk][2*bj4]     = make_float4(b0, b0, b1, b1);
        *(float4*)&Bs2[bk][2*bj4 + 4] = make_float4(b2, b2, b3, b3);
        __syncthreads();
        #pragma unroll
        for (int k = 0; k < 16; k++) {
            ulonglong2 a01 = *(const ulonglong2*)&As[k][ty*4];     // pairs (r0,r1),(r2,r3)
            ulonglong2 bA  = *(const ulonglong2*)&Bs2[k][tx*8];    // cols c0,c1 duplicated
            ulonglong2 bB  = *(const ulonglong2*)&Bs2[k][tx*8+4];  // cols c2,c3 duplicated
            acc[0][0] = fma2(a01.x, bA.x, acc[0][0]);
            acc[1][0] = fma2(a01.y, bA.x, acc[1][0]);
            acc[0][1] = fma2(a01.x, bA.y, acc[0][1]);
            acc[1][1] = fma2(a01.y, bA.y, acc[1][1]);
            acc[0][2] = fma2(a01.x, bB.x, acc[0][2]);
            acc[1][2] = fma2(a01.y, bB.x, acc[1][2]);
            acc[0][3] = fma2(a01.x, bB.y, acc[0][3]);
            acc[1][3] = fma2(a01.y, bB.y, acc[1][3]);
        }
        __syncthreads();
    }

    // epilogue: +Tsq +bias, tanh -> sSum
    int qrow[4];
    #pragma unroll
    for (int i = 0; i < 4; i++) qrow[i] = qd[row0 + ty*4 + i];
    #pragma unroll
    for (int p = 0; p < 2; p++) {
        #pragma unroll
        for (int c = 0; c < 4; c++) {
            int col = tx*4 + c;
            if (col < DF_) {
                float lo, hi;
                unpack2(acc[p][c], lo, hi);
                float bias = sb[col];
                int r0w = ty*4 + 2*p;
                sSum[r0w  ][col] = tanhf(lo + g_Tsq[qrow[2*p  ]*DF_ + col] + bias);
                sSum[r0w+1][col] = tanhf(hi + g_Tsq[qrow[2*p+1]*DF_ + col] + bias);
            }
        }
    }
    __syncthreads();

    // heads: one thread per row
    if (tid < 64) {
        int i = row0 + tid;
        int q = qd[i];
        float th = 0.f, ap = 0.f, l0 = 0.f, l1 = 0.f, l2 = 0.f, l3 = 0.f;
        #pragma unroll 10
        for (int k = 0; k < DF_; k++) {
            float s = sSum[tid][k];
            th = fmaf(s, sAb[k], th);
            ap = fmaf(s, sDw[k], ap);
            l0 = fmaf(s, sCw[k*4+0], l0);
            l1 = fmaf(s, sCw[k*4+1], l1);
            l2 = fmaf(s, sCw[k*4+2], l2);
            l3 = fmaf(s, sCw[k*4+3], l3);
        }
        float theta = (th + __ldg(abB)) * 3.0f;
        ap += g_Tdisc[q];
        float alpha = (ap > 20.f) ? ap : log1pf(expf(ap));
        float4 tc = *(const float4*)&g_Tcorn[q*4];
        l0 += tc.x; l1 += tc.y; l2 += tc.z; l3 += tc.w;
        float cp0 = sigmoidf_(l0);
        float cp1 = cp0 * sigmoidf_(l1);
        float cp2 = cp1 * sigmoidf_(l2);
        float cp3 = cp2 * sigmoidf_(l3);
        const int BT = BT_;
        out[i] = theta;
        *(float4*)&out[BT + 4*i] = *(const float4*)&g_Tbeta[q*4];
        out[5*BT + i] = alpha;
        float* pp = out + 6*BT + 5*i;
        pp[0] = 1.f - cp0; pp[1] = cp0 - cp1; pp[2] = cp1 - cp2;
        pp[3] = cp2 - cp3; pp[4] = cp3;
        *(float4*)&out[11*BT + 4*i] = make_float4(l0, l1, l2, l3);
    }
}

// ---------------- launch ----------------
extern "C" void kernel_launch(void* const* d_in, const int* in_sizes, int n_in,
                              void* d_out, int out_size) {
    const int*   q_data    = (const int*)  d_in[0];
    const int*   r_data    = (const int*)  d_in[1];
    const float* q_embed_W = (const float*)d_in[2];
    const float* Mk        = (const float*)d_in[3];
    const float* Mv0       = (const float*)d_in[4];
    const float* value_W   = (const float*)d_in[5];
    const float* value_b   = (const float*)d_in[6];
    const float* erase_W   = (const float*)d_in[7];
    const float* erase_b   = (const float*)d_in[8];
    const float* add_W     = (const float*)d_in[9];
    const float* add_b     = (const float*)d_in[10];
    const float* summary_W = (const float*)d_in[11];
    const float* summary_b = (const float*)d_in[12];
    const float* ability_W = (const float*)d_in[13];
    const float* ability_b = (const float*)d_in[14];
    const float* thresh_W  = (const float*)d_in[15];
    const float* thresh_b  = (const float*)d_in[16];
    const float* disc_W    = (const float*)d_in[17];
    const float* disc_b    = (const float*)d_in[18];
    const float* corn_W    = (const float*)d_in[19];
    const float* corn_b    = (const float*)d_in[20];
    float* out = (float*)d_out;

    // Launch order keeps scan_kernel as the 4th launch -> ncu capture slot.
    p2_etables<<<126, 256>>>(value_W, erase_W, add_W, value_b, erase_b, add_b);
    p1_qtables<<<NQ_+1, 128>>>(q_embed_W, Mk, summary_W,
                               thresh_W, thresh_b, disc_W, disc_b, corn_W, corn_b);
    p3_acts<<<(NQ_+1)*K_, 256>>>();
    scan_kernel<<<dim3(2, B_), 128>>>(q_data, r_data, Mv0);
    summary_heads<<<BT_/64, 256>>>(summary_W, summary_b, q_data,
                                   ability_W, ability_b, disc_W, corn_W, out);
}

// round 6
// speedup vs baseline: 1.2762x; 1.2762x over previous
#include <cuda_runtime.h>
#include <cstdint>

// Problem constants
#define B_  512
#define T_  512
#define NQ_ 1000
#define K_  5
#define M_  50
#define DK_ 64
#define DV_ 256
#define DF_ 50
#define BT_ (B_*T_)   // 262144

// ---------------- scratch (device globals; no allocation allowed) ----------------
__device__ __align__(16) float g_Tw   [(NQ_+1)*M_];      // softmaxed attention per q
__device__ __align__(16) float g_Tsq  [(NQ_+1)*DF_];     // qe @ summary_W[256:]
__device__ __align__(16) float g_Tbeta[(NQ_+1)*4];       // qe @ thresh_W + b
__device__ __align__(16) float g_Tdisc[(NQ_+1)];         // qe @ disc_W[50:] + b
__device__ __align__(16) float g_Tcorn[(NQ_+1)*4];       // qe @ corn_W[50:] + b
__device__ __align__(16) float g_E1[NQ_*DV_], g_E2[NQ_*DV_];
__device__ __align__(16) float g_A1[NQ_*DV_], g_A2[NQ_*DV_];
__device__ __align__(16) float g_be[DV_], g_ba[DV_];
__device__ __align__(16) float g_Te[(NQ_+1)*K_*DV_];     // sigmoid(erase pre) per (q,r)
__device__ __align__(16) float g_Ta[(NQ_+1)*K_*DV_];     // tanh(add pre)  per (q,r)
__device__ __align__(16) float g_reads  [BT_*DV_];       // 268 MB
__device__ __align__(16) float g_summary[BT_*DF_];       // 52 MB

__device__ __forceinline__ float sigmoidf_(float x) { return 1.f/(1.f+expf(-x)); }

// ---- packed f32x2 helpers (FFMA2 path — only reachable via PTX) ----
typedef unsigned long long ull;
__device__ __forceinline__ ull fma2(ull a, ull b, ull c) {
    ull d; asm("fma.rn.f32x2 %0, %1, %2, %3;" : "=l"(d) : "l"(a), "l"(b), "l"(c));
    return d;
}
__device__ __forceinline__ ull add2(ull a, ull b) {
    ull d; asm("add.rn.f32x2 %0, %1, %2;" : "=l"(d) : "l"(a), "l"(b));
    return d;
}
__device__ __forceinline__ ull pack2(float lo, float hi) {
    ull d; asm("mov.b64 %0, {%1, %2};" : "=l"(d) : "f"(lo), "f"(hi));
    return d;
}
__device__ __forceinline__ void unpack2(ull v, float& lo, float& hi) {
    asm("mov.b64 {%0, %1}, %2;" : "=f"(lo), "=f"(hi) : "l"(v));
}

// ---------------- P2': value_W @ {erase_W, add_W}, plus bias block ----------------
__global__ void p2_etables(const float* __restrict__ vW,
                           const float* __restrict__ We, const float* __restrict__ Wa,
                           const float* __restrict__ vb, const float* __restrict__ eb,
                           const float* __restrict__ ab) {
    __shared__ float vr1[8][DV_];
    __shared__ float vr2[8][DV_];
    int tid = threadIdx.x;
    if (blockIdx.x == 125) {            // bias path
        __shared__ float svb[DV_];
        svb[tid] = vb[tid];
        __syncthreads();
        float e = eb[tid], a = ab[tid];
        for (int k = 0; k < DV_; k++) {
            float x = svb[k];
            e = fmaf(x, We[k*DV_+tid], e);
            a = fmaf(x, Wa[k*DV_+tid], a);
        }
        g_be[tid] = e; g_ba[tid] = a;
        return;
    }
    int i0 = blockIdx.x * 8;
    #pragma unroll
    for (int i = 0; i < 8; i++) {
        vr1[i][tid] = vW[(i0+i)*DV_ + tid];
        vr2[i][tid] = vW[(NQ_ + i0+i)*DV_ + tid];
    }
    __syncthreads();
    float e1[8] = {0}, e2[8] = {0}, a1[8] = {0}, a2[8] = {0};
    int v = tid;
    for (int k = 0; k < DV_; k++) {
        float we = We[k*DV_ + v];
        float wa = Wa[k*DV_ + v];
        #pragma unroll
        for (int i = 0; i < 8; i++) {
            float x1 = vr1[i][k], x2 = vr2[i][k];
            e1[i] = fmaf(x1, we, e1[i]); e2[i] = fmaf(x2, we, e2[i]);
            a1[i] = fmaf(x1, wa, a1[i]); a2[i] = fmaf(x2, wa, a2[i]);
        }
    }
    #pragma unroll
    for (int i = 0; i < 8; i++) {
        g_E1[(i0+i)*DV_ + v] = e1[i]; g_E2[(i0+i)*DV_ + v] = e2[i];
        g_A1[(i0+i)*DV_ + v] = a1[i]; g_A2[(i0+i)*DV_ + v] = a2[i];
    }
}

// ---------------- P1: per-question tables ----------------
__global__ void p1_qtables(const float* __restrict__ qW, const float* __restrict__ Mk,
                           const float* __restrict__ sW,
                           const float* __restrict__ tW, const float* __restrict__ tb,
                           const float* __restrict__ dW, const float* __restrict__ db,
                           const float* __restrict__ cW, const float* __restrict__ cb) {
    __shared__ float qe[DK_];
    __shared__ float wl[M_];
    __shared__ float red[2];
    int q = blockIdx.x, tid = threadIdx.x;
    if (tid < DK_) qe[tid] = qW[q*DK_ + tid];
    __syncthreads();
    if (tid < 50) {
        float acc = 0.f;
        const float* mk = Mk + tid*DK_;
        #pragma unroll 16
        for (int k = 0; k < DK_; k++) acc = fmaf(qe[k], mk[k], acc);
        wl[tid] = acc;
    } else if (tid < 100) {
        int j = tid - 50; float acc = 0.f;
        for (int k = 0; k < DK_; k++) acc = fmaf(qe[k], sW[(DV_+k)*DF_ + j], acc);
        g_Tsq[q*DF_ + j] = acc;
    } else if (tid < 104) {
        int c = tid - 100; float acc = tb[c];
        for (int k = 0; k < DK_; k++) acc = fmaf(qe[k], tW[k*4 + c], acc);
        g_Tbeta[q*4 + c] = acc;
    } else if (tid == 104) {
        float acc = db[0];
        for (int k = 0; k < DK_; k++) acc = fmaf(qe[k], dW[50 + k], acc);
        g_Tdisc[q] = acc;
    } else if (tid < 109) {
        int c = tid - 105; float acc = cb[c];
        for (int k = 0; k < DK_; k++) acc = fmaf(qe[k], cW[(50+k)*4 + c], acc);
        g_Tcorn[q*4 + c] = acc;
    }
    __syncthreads();
    if (tid == 0) {
        float mx = wl[0];
        for (int m = 1; m < M_; m++) mx = fmaxf(mx, wl[m]);
        red[0] = mx;
    }
    __syncthreads();
    if (tid < M_) wl[tid] = expf(wl[tid] - red[0]);
    __syncthreads();
    if (tid == 0) {
        float s = 0.f;
        for (int m = 0; m < M_; m++) s += wl[m];
        red[1] = 1.f / s;
    }
    __syncthreads();
    if (tid < M_) g_Tw[q*M_ + tid] = wl[tid] * red[1];
}

// ---------------- P3: activation tables per (q,r) ----------------
__global__ void p3_acts() {
    int q = blockIdx.x / K_, r = blockIdx.x % K_;
    int v = threadIdx.x;
    float rs = (float)r * 0.25f;
    float pe = 0.f, pa = 0.f;
    if (q > 0) {
        int idx = q - 1;
        pe = fmaf(rs, g_E2[idx*DV_ + v], g_E1[idx*DV_ + v]);
        pa = fmaf(rs, g_A2[idx*DV_ + v], g_A1[idx*DV_ + v]);
    }
    pe += g_be[v]; pa += g_ba[v];
    int base = (q*K_ + r)*DV_ + v;
    g_Te[base] = sigmoidf_(pe);
    g_Ta[base] = tanhf(pa);
}

// ---------------- Scan v5: pack over m + distance-2 pipelining ------------------
// Thread owns a SINGLE v column; Mv2[j] packs {Mv[2j][v], Mv[2j+1][v]}.
// w: 3-buffer smem, staged via register (LDG at t, STS at t+1, read at t+2).
// e/a: registers, loaded 2 steps ahead.
__global__ __launch_bounds__(128, 4) void scan_kernel(const int* __restrict__ qd,
                                                      const int* __restrict__ rd,
                                                      const float* __restrict__ Mv0) {
    __shared__ __align__(16) float w_s[3][52];   // 50 used per buffer
    int b   = blockIdx.y;
    int vb  = blockIdx.x;
    int tid = threadIdx.x;
    int v   = vb*128 + tid;
    ull Mv2[25];
    #pragma unroll
    for (int j = 0; j < 25; j++)
        Mv2[j] = pack2(Mv0[(2*j)*DV_ + v], Mv0[(2*j+1)*DV_ + v]);
    const int bT = b * T_;
    const int* qp = qd + bT;
    const int* rp = rd + bT;
    float* rout = g_reads + (size_t)bT * DV_ + v;

    int q0 = __ldg(qp + 0), r0 = __ldg(rp + 0);
    int q1 = __ldg(qp + 1), r1 = __ldg(rp + 1);
    // prefill: w(t=0) directly; w(t=1) staged in wcur (STS'd at iter 0)
    float wcur = 0.f;
    if (tid < 50) {
        w_s[0][tid] = g_Tw[q0*M_ + tid];
        wcur        = g_Tw[q1*M_ + tid];
    }
    // e/a for t=0, t=1
    float eA = g_Te[(q0*K_ + r0)*DV_ + v];
    float aA = g_Ta[(q0*K_ + r0)*DV_ + v];
    float eB = g_Te[(q1*K_ + r1)*DV_ + v];
    float aB = g_Ta[(q1*K_ + r1)*DV_ + v];
    int qC = __ldg(qp + 2), rC = __ldg(rp + 2);   // indices for t=2
    __syncthreads();

    for (int t = 0; t < T_; t++) {
        // stage w for t+1 into smem; start LDG of w for t+2 into wcur
        if (tid < 50) {
            if (t + 1 < T_) w_s[(t + 1) % 3][tid] = wcur;
            if (t + 2 < T_) wcur = g_Tw[qC*M_ + tid];
        }
        ull ne2 = pack2(-eA, -eA);
        ull a2  = pack2(aA,  aA);
        eA = eB; aA = aB;
        if (t + 2 < T_) {      // LDG e/a for t+2 (consumed at t+2)
            int basen = (qC*K_ + rC)*DV_ + v;
            eB = g_Te[basen];
            aB = g_Ta[basen];
        }
        if (t + 3 < T_) { qC = __ldg(qp + t + 3); rC = __ldg(rp + t + 3); }

        ull acc0 = 0ull, acc1 = 0ull;
        const float* wb = w_s[t % 3];
        #pragma unroll
        for (int j = 0; j < 12; j++) {
            ulonglong2 wv = *(const ulonglong2*)&wb[4*j];  // {w4j,w4j+1},{w4j+2,w4j+3}
            {
                ull old = Mv2[2*j];
                acc0 = fma2(wv.x, old, acc0);
                ull t1 = fma2(old, ne2, a2);
                Mv2[2*j] = fma2(wv.x, t1, old);
            }
            {
                ull old = Mv2[2*j+1];
                acc1 = fma2(wv.y, old, acc1);
                ull t1 = fma2(old, ne2, a2);
                Mv2[2*j+1] = fma2(wv.y, t1, old);
            }
        }
        {   // m = 48,49
            ull wlast = *(const ull*)&wb[48];
            ull old = Mv2[24];
            acc0 = fma2(wlast, old, acc0);
            ull t1 = fma2(old, ne2, a2);
            Mv2[24] = fma2(wlast, t1, old);
        }
        float lo, hi;
        unpack2(add2(acc0, acc1), lo, hi);
        rout[(size_t)t * DV_] = lo + hi;
        __syncthreads();   // readers of buf[(t+1)%3] done next iter; STS drained
    }
}

// ---------------- Summary GEMM: reads[BT,256] @ summary_W[:256,:50], +Tsq, tanh ----
#define GBM 64
#define GBN 64
#define GBK 16
__global__ __launch_bounds__(256) void summary_gemm(const float* __restrict__ sW,
                                                    const float* __restrict__ sb,
                                                    const int* __restrict__ qd) {
    __shared__ __align__(16) float As[GBK][GBM];
    __shared__ __align__(16) float Bs[GBK][GBN];
    int tid = threadIdx.x;
    int brow = blockIdx.x * GBM;
    int tx = tid & 15, ty = tid >> 4;
    int lrow = tid >> 2;            // 0..63
    int lk4  = (tid & 3) * 4;       // 0,4,8,12
    int bk   = tid >> 4;            // 0..15
    int bj4  = (tid & 15) * 4;      // 0..60
    float acc[4][4] = {};
    for (int k0 = 0; k0 < DV_; k0 += GBK) {
        float4 av = *(const float4*)(g_reads + (size_t)(brow + lrow)*DV_ + k0 + lk4);
        As[lk4+0][lrow] = av.x; As[lk4+1][lrow] = av.y;
        As[lk4+2][lrow] = av.z; As[lk4+3][lrow] = av.w;
        int krow = k0 + bk;
        #pragma unroll
        for (int jj = 0; jj < 4; jj++) {
            int j = bj4 + jj;
            Bs[bk][j] = (j < DF_) ? sW[krow*DF_ + j] : 0.f;
        }
        __syncthreads();
        #pragma unroll
        for (int k = 0; k < GBK; k++) {
            float4 a4 = *(const float4*)&As[k][ty*4];
            float4 b4 = *(const float4*)&Bs[k][tx*4];
            float ar[4] = {a4.x, a4.y, a4.z, a4.w};
            float br[4] = {b4.x, b4.y, b4.z, b4.w};
            #pragma unroll
            for (int i = 0; i < 4; i++)
                #pragma unroll
                for (int j = 0; j < 4; j++)
                    acc[i][j] = fmaf(ar[i], br[j], acc[i][j]);
        }
        __syncthreads();
    }
    #pragma unroll
    for (int i = 0; i < 4; i++) {
        int row = brow + ty*4 + i;
        int q = qd[row];
        #pragma unroll
        for (int j = 0; j < 4; j++) {
            int jj = tx*4 + j;
            if (jj < DF_)
                g_summary[(size_t)row*DF_ + jj] =
                    tanhf(acc[i][j] + g_Tsq[q*DF_ + jj] + sb[jj]);
        }
    }
}

// ---------------- Heads ----------------
__global__ __launch_bounds__(128) void heads_kernel(const int* __restrict__ qd,
                                                    const float* __restrict__ abW,
                                                    const float* __restrict__ abB,
                                                    const float* __restrict__ dW,
                                                    const float* __restrict__ cW,
                                                    float* __restrict__ out) {
    __shared__ float sS[128*DF_];
    __shared__ float sAb[DF_], sDw[DF_], sCw[DF_*4];
    int tid = threadIdx.x;
    int base = blockIdx.x * 128;
    for (int idx = tid; idx < 128*DF_; idx += 128)
        sS[idx] = g_summary[(size_t)base*DF_ + idx];
    if (tid < DF_) { sAb[tid] = abW[tid]; sDw[tid] = dW[tid]; }
    for (int idx = tid; idx < DF_*4; idx += 128) sCw[idx] = cW[idx];
    __syncthreads();
    int i = base + tid;
    int q = qd[i];
    float th = 0.f, ap = 0.f, l0 = 0.f, l1 = 0.f, l2 = 0.f, l3 = 0.f;
    #pragma unroll 10
    for (int k = 0; k < DF_; k++) {
        float s = sS[tid*DF_ + k];
        th = fmaf(s, sAb[k], th);
        ap = fmaf(s, sDw[k], ap);
        l0 = fmaf(s, sCw[k*4+0], l0);
        l1 = fmaf(s, sCw[k*4+1], l1);
        l2 = fmaf(s, sCw[k*4+2], l2);
        l3 = fmaf(s, sCw[k*4+3], l3);
    }
    float theta = (th + abB[0]) * 3.0f;
    ap += g_Tdisc[q];
    float alpha = (ap > 20.f) ? ap : log1pf(expf(ap));
    float4 tc = *(const float4*)&g_Tcorn[q*4];
    l0 += tc.x; l1 += tc.y; l2 += tc.z; l3 += tc.w;
    float cp0 = sigmoidf_(l0);
    float cp1 = cp0 * sigmoidf_(l1);
    float cp2 = cp1 * sigmoidf_(l2);
    float cp3 = cp2 * sigmoidf_(l3);
    const int BT = BT_;
    out[i] = theta;
    *(float4*)&out[BT + 4*i] = *(const float4*)&g_Tbeta[q*4];
    out[5*BT + i] = alpha;
    float* pp = out + 6*BT + 5*i;
    pp[0] = 1.f - cp0; pp[1] = cp0 - cp1; pp[2] = cp1 - cp2;
    pp[3] = cp2 - cp3; pp[4] = cp3;
    *(float4*)&out[11*BT + 4*i] = make_float4(l0, l1, l2, l3);
}

// ---------------- launch ----------------
extern "C" void kernel_launch(void* const* d_in, const int* in_sizes, int n_in,
                              void* d_out, int out_size) {
    const int*   q_data    = (const int*)  d_in[0];
    const int*   r_data    = (const int*)  d_in[1];
    const float* q_embed_W = (const float*)d_in[2];
    const float* Mk        = (const float*)d_in[3];
    const float* Mv0       = (const float*)d_in[4];
    const float* value_W   = (const float*)d_in[5];
    const float* value_b   = (const float*)d_in[6];
    const float* erase_W   = (const float*)d_in[7];
    const float* erase_b   = (const float*)d_in[8];
    const float* add_W     = (const float*)d_in[9];
    const float* add_b     = (const float*)d_in[10];
    const float* summary_W = (const float*)d_in[11];
    const float* summary_b = (const float*)d_in[12];
    const float* ability_W = (const float*)d_in[13];
    const float* ability_b = (const float*)d_in[14];
    const float* thresh_W  = (const float*)d_in[15];
    const float* thresh_b  = (const float*)d_in[16];
    const float* disc_W    = (const float*)d_in[17];
    const float* disc_b    = (const float*)d_in[18];
    const float* corn_W    = (const float*)d_in[19];
    const float* corn_b    = (const float*)d_in[20];
    float* out = (float*)d_out;

    // Launch order keeps scan_kernel as the 4th launch -> ncu capture slot.
    p2_etables<<<126, 256>>>(value_W, erase_W, add_W, value_b, erase_b, add_b);
    p1_qtables<<<NQ_+1, 128>>>(q_embed_W, Mk, summary_W,
                               thresh_W, thresh_b, disc_W, disc_b, corn_W, corn_b);
    p3_acts<<<(NQ_+1)*K_, 256>>>();
    scan_kernel<<<dim3(2, B_), 128>>>(q_data, r_data, Mv0);
    summary_gemm<<<BT_/GBM, 256>>>(summary_W, summary_b, q_data);
    heads_kernel<<<BT_/128, 128>>>(q_data, ability_W, ability_b,
                                   disc_W, corn_W, out);
}